// round 17
// baseline (speedup 1.0000x reference)
#include <cuda_runtime.h>
#include <cuda_bf16.h>
#include <cstdint>
#include <math.h>

#define BB 16
#define NN 1024
#define CC 768
#define HH 12
#define DD 64
#define BANKN 256
#define MKEYS (NN + BANKN)   // 1280
#define KC2 32               // fp32 K elems per chunk (128 B rows)
#define NCHUNK2 (CC/KC2)     // 24
#define STRIDE 132
#define TILE_M 256
#define GTHREADS 512
#define STAGE_BYTES 49152    // A 32KB + B 16KB
#define GSMEM (3*STAGE_BYTES)

#define LOG2E 1.44269504088896f

// attention tiling
#define AQ 128
#define ACH 64
#define ANCH (MKEYS/ACH)     // 20
#define SM_K 0               // 2 x [64][68] f32 (tf32 bits, d-pair permuted)
#define SM_V 34816           // 2 x (V_hi 8KB + V_lo 8KB), XOR-swizzled 128B rows
#define VSTAGE 16384
#define ASMEM 67584          // 2 CTAs/SM with headroom

// ---------------- scratch ----------------
__device__ __align__(16) float    g_v[BB*HH*NN*DD];             // v (fp32, [bh][n][d])
__device__ __align__(16) float    g_p[BB*NN*CC];                // proj out, pre-LN
__device__ __align__(16) uint32_t g_xt[(size_t)BB*NN*CC];       // x  (tf32)
__device__ __align__(16) uint32_t g_ot[(size_t)BB*NN*CC];       // attn out (tf32)
__device__ __align__(16) uint32_t g_wqt[(size_t)3*CC*CC];       // qkv_w (tf32)
__device__ __align__(16) uint32_t g_wpt[(size_t)CC*CC];         // proj_w (tf32)
__device__ __align__(16) uint32_t g_qt[(size_t)BB*HH*NN*DD];    // q (tf32, scaled log2e/8)
__device__ __align__(16) uint32_t g_kt[(size_t)BB*HH*MKEYS*DD]; // k + bank (tf32, PERMUTED d-pairs)
__device__ __align__(16) __nv_bfloat16 g_vh[(size_t)BB*HH*DD*MKEYS]; // v hi plane [bh][d][m]
__device__ __align__(16) __nv_bfloat16 g_vl[(size_t)BB*HH*DD*MKEYS]; // v lo plane [bh][d][m]

// ---------------- PTX helpers ----------------
__device__ __forceinline__ uint32_t smem_u32(const void* p) {
    uint32_t a;
    asm("{ .reg .u64 t; cvta.to.shared.u64 t, %1; cvt.u32.u64 %0, t; }" : "=r"(a) : "l"(p));
    return a;
}
__device__ __forceinline__ void cp_async16(uint32_t dst, const void* src) {
    asm volatile("cp.async.cg.shared.global [%0], [%1], 16;" :: "r"(dst), "l"(src));
}
__device__ __forceinline__ void cp_commit() {
    asm volatile("cp.async.commit_group;");
}
template<int N>
__device__ __forceinline__ void cp_wait() {
    asm volatile("cp.async.wait_group %0;" :: "n"(N));
}
__device__ __forceinline__ void ldsm4(uint32_t* r, uint32_t addr) {
    asm volatile("ldmatrix.sync.aligned.m8n8.x4.shared.b16 {%0,%1,%2,%3}, [%4];"
                 : "=r"(r[0]), "=r"(r[1]), "=r"(r[2]), "=r"(r[3]) : "r"(addr));
}
__device__ __forceinline__ void mma16816(float* d, const uint32_t* a, const uint32_t* b) {
    asm volatile(
        "mma.sync.aligned.m16n8k16.row.col.f32.bf16.bf16.f32 "
        "{%0,%1,%2,%3}, {%4,%5,%6,%7}, {%8,%9}, {%0,%1,%2,%3};"
        : "+f"(d[0]), "+f"(d[1]), "+f"(d[2]), "+f"(d[3])
        : "r"(a[0]), "r"(a[1]), "r"(a[2]), "r"(a[3]), "r"(b[0]), "r"(b[1]));
}
__device__ __forceinline__ void mma1688(float* d, const uint32_t* a, const uint32_t* b) {
    asm volatile(
        "mma.sync.aligned.m16n8k8.row.col.f32.tf32.tf32.f32 "
        "{%0,%1,%2,%3}, {%4,%5,%6,%7}, {%8,%9}, {%0,%1,%2,%3};"
        : "+f"(d[0]), "+f"(d[1]), "+f"(d[2]), "+f"(d[3])
        : "r"(a[0]), "r"(a[1]), "r"(a[2]), "r"(a[3]), "r"(b[0]), "r"(b[1]));
}
__device__ __forceinline__ uint32_t tf32c(float f) {
    uint32_t r; asm("cvt.rna.tf32.f32 %0, %1;" : "=r"(r) : "f"(f)); return r;
}
__device__ __forceinline__ float ex2(float x) {
    float r; asm("ex2.approx.ftz.f32 %0, %1;" : "=f"(r) : "f"(x)); return r;
}

// ---------------------------------------------------------------------------
// tf32 pre-rounding (RNA): 0=x->g_xt  1=qkv_w->g_wqt  3=proj_w->g_wpt
// ---------------------------------------------------------------------------
template<int W>
__global__ __launch_bounds__(256)
void convt(const float4* __restrict__ src, int n4)
{
    int i = blockIdx.x * blockDim.x + threadIdx.x;
    if (i >= n4) return;
    uint4* dst = (W == 0) ? (uint4*)g_xt : (W == 1) ? (uint4*)g_wqt : (uint4*)g_wpt;
    float4 v = src[i];
    uint4 o;
    o.x = tf32c(v.x); o.y = tf32c(v.y); o.z = tf32c(v.z); o.w = tf32c(v.w);
    dst[i] = o;
}

// bank_k rows -> g_kt tail (tf32, permuted d-pairs)
__global__ __launch_bounds__(256)
void convkt_bank(const float* __restrict__ bank_k)
{
    int i = blockIdx.x * blockDim.x + threadIdx.x;     // float4 index
    if (i >= BB*HH*BANKN*DD/4) return;
    int c4 = i & 15;
    int m  = (i >> 4) % BANKN;
    int bh = (i >> 4) / BANKN;
    int h  = bh % HH;
    float4 v = *(const float4*)(bank_k + (size_t)m * CC + h * DD + c4 * 4);
    int d0 = c4 * 4;
    int gbase = d0 & ~7;
    int odd = (d0 & 4) ? 1 : 0;
    uint32_t* kt = g_kt + ((size_t)bh * MKEYS + NN + m) * DD + gbase + odd;
    kt[0] = tf32c(v.x); kt[2] = tf32c(v.y); kt[4] = tf32c(v.z); kt[6] = tf32c(v.w);
}

// g_v + bank_v -> V_hi / V_lo planes [bh][d][m] (bf16)
__global__ __launch_bounds__(256)
void convv3(const float* __restrict__ bank_v)
{
    __shared__ float t[64][65];
    const int tid = threadIdx.x;
    const int m0 = blockIdx.x * 64;
    const int bh = blockIdx.y;
    const int h  = bh % HH;
    #pragma unroll
    for (int i = 0; i < 4; i++) {
        int idx = tid + i * 256;
        int m = idx >> 4, d4 = (idx & 15) * 4;
        int gm = m0 + m;
        const float* src = (gm < NN)
            ? g_v + ((size_t)bh*NN + gm)*DD + d4
            : bank_v + (size_t)(gm - NN)*CC + h*DD + d4;
        float4 v = *(const float4*)src;
        t[m][d4] = v.x; t[m][d4+1] = v.y; t[m][d4+2] = v.z; t[m][d4+3] = v.w;
    }
    __syncthreads();
    const int d = tid >> 2, part = tid & 3;
    __nv_bfloat16 bhi[16], blo[16];
    #pragma unroll
    for (int mm = 0; mm < 16; mm++) {
        float f = t[part*16 + mm][d];
        __nv_bfloat16 hi = __float2bfloat16(f);
        __nv_bfloat16 lo = __float2bfloat16(f - __bfloat162float(hi));
        bhi[mm] = hi; blo[mm] = lo;
    }
    size_t base = ((size_t)bh*DD + d)*MKEYS + m0 + part*16;
    uint4* dh = (uint4*)(g_vh + base);
    uint4* dl = (uint4*)(g_vl + base);
    const uint4* sh = (const uint4*)bhi;
    const uint4* sl = (const uint4*)blo;
    dh[0] = sh[0]; dh[1] = sh[1];
    dl[0] = sl[0]; dl[1] = sl[1];
}

// ---------------------------------------------------------------------------
// tf32 GEMM, 256x128 tile, 512 threads, 3-stage cp.async pipeline
// ---------------------------------------------------------------------------
template<int MODE>
__global__ __launch_bounds__(GTHREADS)
void gemm_t(const float* __restrict__ bias)
{
    extern __shared__ __align__(1024) char sm[];
    const uint32_t smb = smem_u32(sm);
    const int tid = threadIdx.x, wid = tid >> 5, lane = tid & 31;
    const int row0 = blockIdx.x * TILE_M, col0 = blockIdx.y * 128;
    const uint32_t* __restrict__ A = (MODE == 0) ? g_xt : g_ot;
    const uint32_t* __restrict__ W = (MODE == 0) ? g_wqt : g_wpt;

    const int wm = wid >> 1;
    const int wn = wid & 1;

    uint32_t abase[2]; uint32_t asw[2];
    #pragma unroll
    for (int mt = 0; mt < 2; mt++) {
        int r = wm * 32 + mt * 16 + (lane & 7) + ((lane >> 3) & 1) * 8;
        abase[mt] = (uint32_t)(r * 128);
        asw[mt]   = (uint32_t)(r & 7);
    }
    uint32_t bbase[4]; uint32_t bsw[4];
    #pragma unroll
    for (int p = 0; p < 4; p++) {
        int r = wn * 64 + p * 16 + (lane & 7) + ((lane >> 4) & 1) * 8;
        bbase[p] = (uint32_t)(r * 128);
        bsw[p]   = (uint32_t)(r & 7);
    }
    const uint32_t ka = (lane >> 4) & 1;
    const uint32_t kb = (lane >> 3) & 1;

    const int lrA = tid >> 1;
    const int luA = (tid & 1) * 4;
    uint32_t stA[4];
    #pragma unroll
    for (int it = 0; it < 4; it++) {
        int u = luA + it;
        stA[it] = (uint32_t)(lrA * 128 + (((uint32_t)u ^ (uint32_t)(lrA & 7)) << 4));
    }
    const int lrB = tid >> 2;
    const int luB = (tid & 3) * 2;
    uint32_t stB[2];
    #pragma unroll
    for (int it = 0; it < 2; it++) {
        int u = luB + it;
        stB[it] = (uint32_t)(lrB * 128 + (((uint32_t)u ^ (uint32_t)(lrB & 7)) << 4));
    }

    float acc[2][8][4];
    #pragma unroll
    for (int mt = 0; mt < 2; mt++)
        #pragma unroll
        for (int nt = 0; nt < 8; nt++)
            #pragma unroll
            for (int c = 0; c < 4; c++) acc[mt][nt][c] = 0.0f;

    #pragma unroll
    for (int pre = 0; pre < 2; pre++) {
        const uint32_t pbuf = smb + pre * STAGE_BYTES;
        const uint32_t* Asrc = A + (size_t)row0 * CC + pre * KC2;
        const uint32_t* Wsrc = W + (size_t)col0 * CC + pre * KC2;
        #pragma unroll
        for (int it = 0; it < 4; it++)
            cp_async16(pbuf + stA[it], Asrc + (size_t)lrA * CC + (luA + it) * 4);
        #pragma unroll
        for (int it = 0; it < 2; it++)
            cp_async16(pbuf + 32768 + stB[it], Wsrc + (size_t)lrB * CC + (luB + it) * 4);
        cp_commit();
    }

    int bufsel = 0;
    for (int ch = 0; ch < NCHUNK2; ch++) {
        const uint32_t buf = smb + bufsel * STAGE_BYTES;
        if (ch + 2 < NCHUNK2) {
            int nb = bufsel + 2; if (nb >= 3) nb -= 3;
            const uint32_t nbuf = smb + nb * STAGE_BYTES;
            const uint32_t* Asrc = A + (size_t)row0 * CC + (ch + 2) * KC2;
            const uint32_t* Wsrc = W + (size_t)col0 * CC + (ch + 2) * KC2;
            #pragma unroll
            for (int it = 0; it < 4; it++)
                cp_async16(nbuf + stA[it], Asrc + (size_t)lrA * CC + (luA + it) * 4);
            #pragma unroll
            for (int it = 0; it < 2; it++)
                cp_async16(nbuf + 32768 + stB[it], Wsrc + (size_t)lrB * CC + (luB + it) * 4);
            cp_commit();
            cp_wait<2>();
        } else if (ch + 1 < NCHUNK2) {
            cp_wait<1>();
        } else {
            cp_wait<0>();
        }
        __syncthreads();

        #pragma unroll
        for (int ks = 0; ks < 4; ks++) {
            uint32_t af[2][4], bf[4][4];
            const uint32_t ga = ka + 2 * ks;
            const uint32_t gb = kb + 2 * ks;
            #pragma unroll
            for (int mt = 0; mt < 2; mt++)
                ldsm4(af[mt], buf + abase[mt] + ((ga ^ asw[mt]) << 4));
            #pragma unroll
            for (int p = 0; p < 4; p++)
                ldsm4(bf[p], buf + 32768 + bbase[p] + ((gb ^ bsw[p]) << 4));
            #pragma unroll
            for (int mt = 0; mt < 2; mt++)
                #pragma unroll
                for (int p = 0; p < 4; p++) {
                    mma1688(acc[mt][2*p],     af[mt], &bf[p][0]);
                    mma1688(acc[mt][2*p + 1], af[mt], &bf[p][2]);
                }
        }
        __syncthreads();
        if (++bufsel == 3) bufsel = 0;
    }

    float* stage = (float*)sm;
    const int g   = lane >> 2;
    const int tp  = (lane & 3) * 2;
    #pragma unroll
    for (int mt = 0; mt < 2; mt++) {
        int rbase = wm * 32 + mt * 16 + g;
        #pragma unroll
        for (int nt = 0; nt < 8; nt++) {
            int cbase = wn * 64 + nt * 8 + tp;
            stage[rbase * STRIDE + cbase]           = acc[mt][nt][0];
            stage[rbase * STRIDE + cbase + 1]       = acc[mt][nt][1];
            stage[(rbase + 8) * STRIDE + cbase]     = acc[mt][nt][2];
            stage[(rbase + 8) * STRIDE + cbase + 1] = acc[mt][nt][3];
        }
    }
    __syncthreads();

    #pragma unroll
    for (int it = 0; it < 16; it++) {
        int idx = tid + it * GTHREADS;
        int r = idx >> 5, q = idx & 31, c = q * 4;
        float4 v = *(float4*)&stage[r * STRIDE + c];
        int f0 = col0 + c;
        v.x += bias[f0]; v.y += bias[f0 + 1]; v.z += bias[f0 + 2]; v.w += bias[f0 + 3];
        int gr = row0 + r;
        if (MODE == 0) {
            int b = gr >> 10, n = gr & 1023;
            int which = f0 / CC;
            int hd = f0 - which * CC;
            int h = hd >> 6, d = hd & 63;
            int bh = b * HH + h;
            if (which == 0) {
                const float qs = 0.125f * LOG2E;
                uint4 o;
                o.x = tf32c(v.x * qs); o.y = tf32c(v.y * qs);
                o.z = tf32c(v.z * qs); o.w = tf32c(v.w * qs);
                *(uint4*)&g_qt[((size_t)bh * NN + n) * DD + d] = o;
            } else if (which == 1) {
                // permuted d-pair layout: group of 8, phys = 2*(p&3) + (p>>2)
                int gbase = d & ~7;
                int odd = (d & 4) ? 1 : 0;
                uint32_t* kt = g_kt + ((size_t)bh * MKEYS + n) * DD + gbase + odd;
                kt[0] = tf32c(v.x); kt[2] = tf32c(v.y);
                kt[4] = tf32c(v.z); kt[6] = tf32c(v.w);
            } else {
                *(float4*)&g_v[((size_t)bh * NN + n) * DD + d] = v;
            }
        } else {
            *(float4*)&g_p[(size_t)gr * CC + f0] = v;
        }
    }
}

// ---------------------------------------------------------------------------
// Flash attention: tf32 QK^T (exp2) + 3x-bf16-split PV, register P.
// Q hoisted to registers via LDG (no Q smem). K b-pairs via LDS.64 on
// permuted g_kt. 67.6 KB smem, 2 CTAs/SM.
// ---------------------------------------------------------------------------
__global__ __launch_bounds__(256, 2)
void attn2(float* __restrict__ out)
{
    extern __shared__ __align__(16) char sm[];
    const uint32_t smb = smem_u32(sm);
    const int tid = threadIdx.x, w = tid >> 5, lane = tid & 31;
    const int g = lane >> 2, c = lane & 3;
    const int bh = blockIdx.y, q0 = blockIdx.x * AQ;
    const int b = bh / HH, h = bh - b * HH;

    // ldsm V fragment addressing (gemm-style XOR swizzle, 128B rows)
    uint32_t vbase[4], vsw[4];
    #pragma unroll
    for (int p = 0; p < 4; p++) {
        int vr = p * 16 + (lane & 7) + ((lane >> 4) & 1) * 8;
        vbase[p] = (uint32_t)(vr * 128);
        vsw[p]   = (uint32_t)(vr & 7);
    }
    const uint32_t kbv = (lane >> 3) & 1;

    const __nv_bfloat16* vhsrc = g_vh + (size_t)bh * DD * MKEYS;
    const __nv_bfloat16* vlsrc = g_vl + (size_t)bh * DD * MKEYS;

    // ---- prologue loads: K chunk0 + V chunk0 (cp.async)
    {
        const uint32_t* ks = g_kt + (size_t)bh * MKEYS * DD;
        #pragma unroll
        for (int i = 0; i < 4; i++) {
            int idx = tid + i * 256;
            int r = idx >> 4, c16 = idx & 15;
            cp_async16(smb + SM_K + r * 272 + c16 * 16, ks + (size_t)r * DD + c16 * 4);
        }
        #pragma unroll
        for (int i = 0; i < 4; i++) {
            int idx = tid + i * 256;          // 0..1023
            int half = idx >> 9, rem = idx & 511;
            int r = rem >> 3, u = rem & 7;
            const __nv_bfloat16* src2 = (half ? vlsrc : vhsrc) + (size_t)r * MKEYS + u * 8;
            cp_async16(smb + SM_V + half * 8192 + r * 128 + (((uint32_t)u ^ (uint32_t)(r & 7)) << 4),
                       src2);
        }
        cp_commit();
    }

    // ---- Q fragments via direct LDG (one-time, L2-resident)
    uint32_t qfrag[8][4];
    {
        const uint32_t* q0p = g_qt + ((size_t)bh * NN + q0 + 16 * w + g) * DD;
        const uint32_t* q1p = q0p + 8 * DD;
        #pragma unroll
        for (int ks = 0; ks < 8; ks++) {
            qfrag[ks][0] = q0p[ks * 8 + c];
            qfrag[ks][1] = q1p[ks * 8 + c];
            qfrag[ks][2] = q0p[ks * 8 + c + 4];
            qfrag[ks][3] = q1p[ks * 8 + c + 4];
        }
    }

    float mprev0 = -INFINITY, mprev1 = -INFINITY, l0 = 0.0f, l1 = 0.0f;
    float o[8][4];
    #pragma unroll
    for (int t = 0; t < 8; t++)
        #pragma unroll
        for (int j = 0; j < 4; j++) o[t][j] = 0.0f;

    for (int ch = 0; ch < ANCH; ch++) {
        const int buf = ch & 1;
        if (ch + 1 < ANCH) {
            const int nb = buf ^ 1;
            const uint32_t* ks = g_kt + ((size_t)bh * MKEYS + (ch + 1) * ACH) * DD;
            #pragma unroll
            for (int i = 0; i < 4; i++) {
                int idx = tid + i * 256;
                int r = idx >> 4, c16 = idx & 15;
                cp_async16(smb + SM_K + nb * 17408 + r * 272 + c16 * 16,
                           ks + (size_t)r * DD + c16 * 4);
            }
            const int m0 = (ch + 1) * ACH;
            #pragma unroll
            for (int i = 0; i < 4; i++) {
                int idx = tid + i * 256;
                int half = idx >> 9, rem = idx & 511;
                int r = rem >> 3, u = rem & 7;
                const __nv_bfloat16* src2 = (half ? vlsrc : vhsrc) + (size_t)r * MKEYS + m0 + u * 8;
                cp_async16(smb + SM_V + nb * VSTAGE + half * 8192 + r * 128 +
                               (((uint32_t)u ^ (uint32_t)(r & 7)) << 4),
                           src2);
            }
            cp_commit();
            cp_wait<1>();
        } else {
            cp_wait<0>();
        }
        __syncthreads();

        // ---- S = Q K^T (tf32, log2 domain); K pairs via LDS.64 (permuted)
        const uint32_t* Ks = (const uint32_t*)(sm + SM_K + buf * 17408);
        float sacc[8][4];
        #pragma unroll
        for (int t = 0; t < 8; t++)
            #pragma unroll
            for (int j = 0; j < 4; j++) sacc[t][j] = 0.0f;

        #pragma unroll
        for (int ks = 0; ks < 8; ks++) {
            #pragma unroll
            for (int t = 0; t < 8; t++) {
                uint2 bp = *(const uint2*)(Ks + (t * 8 + g) * 68 + ks * 8 + 2 * c);
                mma1688(sacc[t], qfrag[ks], (const uint32_t*)&bp);
            }
        }

        // ---- online softmax (exp2); p values back into sacc
        float mx0 = -INFINITY, mx1 = -INFINITY;
        #pragma unroll
        for (int t = 0; t < 8; t++) {
            mx0 = fmaxf(mx0, fmaxf(sacc[t][0], sacc[t][1]));
            mx1 = fmaxf(mx1, fmaxf(sacc[t][2], sacc[t][3]));
        }
        mx0 = fmaxf(mx0, __shfl_xor_sync(0xffffffffu, mx0, 1));
        mx0 = fmaxf(mx0, __shfl_xor_sync(0xffffffffu, mx0, 2));
        mx1 = fmaxf(mx1, __shfl_xor_sync(0xffffffffu, mx1, 1));
        mx1 = fmaxf(mx1, __shfl_xor_sync(0xffffffffu, mx1, 2));
        const float mnew0 = fmaxf(mprev0, mx0);
        const float mnew1 = fmaxf(mprev1, mx1);
        const float alpha0 = ex2(mprev0 - mnew0);
        const float alpha1 = ex2(mprev1 - mnew1);

        float ps0 = 0.0f, ps1 = 0.0f;
        #pragma unroll
        for (int t = 0; t < 8; t++) {
            float p0 = ex2(sacc[t][0] - mnew0);
            float p1 = ex2(sacc[t][1] - mnew0);
            float p2 = ex2(sacc[t][2] - mnew1);
            float p3 = ex2(sacc[t][3] - mnew1);
            ps0 += p0 + p1; ps1 += p2 + p3;
            sacc[t][0] = p0; sacc[t][1] = p1; sacc[t][2] = p2; sacc[t][3] = p3;
        }
        ps0 += __shfl_xor_sync(0xffffffffu, ps0, 1);
        ps0 += __shfl_xor_sync(0xffffffffu, ps0, 2);
        ps1 += __shfl_xor_sync(0xffffffffu, ps1, 1);
        ps1 += __shfl_xor_sync(0xffffffffu, ps1, 2);
        l0 = l0 * alpha0 + ps0; l1 = l1 * alpha1 + ps1;
        mprev0 = mnew0; mprev1 = mnew1;
        #pragma unroll
        for (int t = 0; t < 8; t++) {
            o[t][0] *= alpha0; o[t][1] *= alpha0;
            o[t][2] *= alpha1; o[t][3] *= alpha1;
        }

        // ---- O += P_hi*V_hi + P_hi*V_lo + P_lo*V_hi  (register-resident P)
        const uint32_t vstage = smb + SM_V + buf * VSTAGE;
        #pragma unroll
        for (int u = 0; u < 4; u++) {
            const float* p0 = sacc[2*u];
            const float* p1 = sacc[2*u + 1];
            uint32_t h00 = __float_as_uint(p0[0]), h01 = __float_as_uint(p0[1]);
            uint32_t h02 = __float_as_uint(p0[2]), h03 = __float_as_uint(p0[3]);
            uint32_t h10 = __float_as_uint(p1[0]), h11 = __float_as_uint(p1[1]);
            uint32_t h12 = __float_as_uint(p1[2]), h13 = __float_as_uint(p1[3]);
            uint32_t pa[4], pl[4];
            pa[0] = __byte_perm(h00, h01, 0x7632);
            pa[1] = __byte_perm(h02, h03, 0x7632);
            pa[2] = __byte_perm(h10, h11, 0x7632);
            pa[3] = __byte_perm(h12, h13, 0x7632);
            float l00f = p0[0] - __uint_as_float(h00 & 0xFFFF0000u);
            float l01f = p0[1] - __uint_as_float(h01 & 0xFFFF0000u);
            float l02f = p0[2] - __uint_as_float(h02 & 0xFFFF0000u);
            float l03f = p0[3] - __uint_as_float(h03 & 0xFFFF0000u);
            float l10f = p1[0] - __uint_as_float(h10 & 0xFFFF0000u);
            float l11f = p1[1] - __uint_as_float(h11 & 0xFFFF0000u);
            float l12f = p1[2] - __uint_as_float(h12 & 0xFFFF0000u);
            float l13f = p1[3] - __uint_as_float(h13 & 0xFFFF0000u);
            pl[0] = __byte_perm(__float_as_uint(l00f), __float_as_uint(l01f), 0x7632);
            pl[1] = __byte_perm(__float_as_uint(l02f), __float_as_uint(l03f), 0x7632);
            pl[2] = __byte_perm(__float_as_uint(l10f), __float_as_uint(l11f), 0x7632);
            pl[3] = __byte_perm(__float_as_uint(l12f), __float_as_uint(l13f), 0x7632);

            const uint32_t gbv = kbv + 2 * (uint32_t)u;
            #pragma unroll
            for (int p = 0; p < 4; p++) {
                uint32_t off = vbase[p] + ((gbv ^ vsw[p]) << 4);
                uint32_t vh[4], vl[4];
                ldsm4(vh, vstage + off);
                ldsm4(vl, vstage + 8192 + off);
                mma16816(o[2*p],     pa, &vh[0]);
                mma16816(o[2*p + 1], pa, &vh[2]);
                mma16816(o[2*p],     pa, &vl[0]);
                mma16816(o[2*p + 1], pa, &vl[2]);
                mma16816(o[2*p],     pl, &vh[0]);
                mma16816(o[2*p + 1], pl, &vh[2]);
            }
        }
        __syncthreads();
    }

    // ---- normalize + write out (fp32) and g_ot (tf32)
    const float inv0 = 1.0f / l0, inv1 = 1.0f / l1;
    const int n0 = q0 + 16 * w + g, n1 = n0 + 8;
    #pragma unroll
    for (int t = 0; t < 8; t++) {
        int col = h * DD + 8 * t + 2 * c;
        float v00 = o[t][0] * inv0, v01 = o[t][1] * inv0;
        float v10 = o[t][2] * inv1, v11 = o[t][3] * inv1;
        *(float2*)&out[((size_t)b * NN + n0) * CC + col] = make_float2(v00, v01);
        *(float2*)&out[((size_t)b * NN + n1) * CC + col] = make_float2(v10, v11);
        uint2 t0; t0.x = tf32c(v00); t0.y = tf32c(v01);
        uint2 t1; t1.x = tf32c(v10); t1.y = tf32c(v11);
        *(uint2*)&g_ot[((size_t)b * NN + n0) * CC + col] = t0;
        *(uint2*)&g_ot[((size_t)b * NN + n1) * CC + col] = t1;
    }
}

// ---------------------------------------------------------------------------
__global__ __launch_bounds__(256)
void ln_kernel(const float* __restrict__ nw, const float* __restrict__ nb,
               float* __restrict__ outb)
{
    __shared__ float shs[8], shs2[8];
    const int row = blockIdx.x;
    const int tid = threadIdx.x;
    const float* pr = g_p + (size_t)row * CC;

    float v[3];
    float s = 0.0f, s2 = 0.0f;
    #pragma unroll
    for (int i = 0; i < 3; i++) {
        v[i] = pr[tid + i * 256];
        s  += v[i];
        s2 += v[i] * v[i];
    }
    #pragma unroll
    for (int off = 16; off >= 1; off >>= 1) {
        s  += __shfl_xor_sync(0xffffffffu, s,  off);
        s2 += __shfl_xor_sync(0xffffffffu, s2, off);
    }
    if ((tid & 31) == 0) { shs[tid >> 5] = s; shs2[tid >> 5] = s2; }
    __syncthreads();
    float ts = 0.0f, ts2 = 0.0f;
    #pragma unroll
    for (int w = 0; w < 8; w++) { ts += shs[w]; ts2 += shs2[w]; }

    const float mu  = ts * (1.0f / CC);
    const float var = ts2 * (1.0f / CC) - mu * mu;
    const float r   = rsqrtf(var + 1e-5f);

    #pragma unroll
    for (int i = 0; i < 3; i++) {
        int c = tid + i * 256;
        outb[(size_t)row * CC + c] = (v[i] - mu) * r * nw[c] + nb[c];
    }
}

// ---------------------------------------------------------------------------
extern "C" void kernel_launch(void* const* d_in, const int* in_sizes, int n_in,
                              void* d_out, int out_size)
{
    const float* x      = (const float*)d_in[0];
    const float* qkv_w  = (const float*)d_in[1];
    const float* qkv_b  = (const float*)d_in[2];
    const float* proj_w = (const float*)d_in[3];
    const float* proj_b = (const float*)d_in[4];
    const float* norm_w = (const float*)d_in[5];
    const float* norm_b = (const float*)d_in[6];
    const float* bank_k = (const float*)d_in[7];
    const float* bank_v = (const float*)d_in[8];

    float* out      = (float*)d_out;
    float* bank_upd = out + (size_t)BB * NN * CC;

    cudaFuncSetAttribute(attn2, cudaFuncAttributeMaxDynamicSharedMemorySize, ASMEM);
    cudaFuncSetAttribute(gemm_t<0>, cudaFuncAttributeMaxDynamicSharedMemorySize, GSMEM);
    cudaFuncSetAttribute(gemm_t<1>, cudaFuncAttributeMaxDynamicSharedMemorySize, GSMEM);

    const int nx4  = BB * NN * CC / 4;
    const int nwq4 = 3 * CC * CC / 4;
    const int nwp4 = CC * CC / 4;
    const int nbk4 = BB * HH * BANKN * DD / 4;

    // order chosen so gemm_t<0> is launch #4 (ncu capture slot)
    convt<0><<<(nx4 + 255) / 256, 256>>>((const float4*)x, nx4);
    convt<1><<<(nwq4 + 255) / 256, 256>>>((const float4*)qkv_w, nwq4);
    convt<3><<<(nwp4 + 255) / 256, 256>>>((const float4*)proj_w, nwp4);
    gemm_t<0><<<dim3(BB*NN/TILE_M, 18), GTHREADS, GSMEM>>>(qkv_b);
    convkt_bank<<<(nbk4 + 255) / 256, 256>>>(bank_k);
    convv3<<<dim3(ANCH, BB*HH), 256>>>(bank_v);
    attn2<<<dim3(NN / AQ, BB * HH), 256, ASMEM>>>(out);
    gemm_t<1><<<dim3(BB*NN/TILE_M, 6), GTHREADS, GSMEM>>>(proj_b);
    ln_kernel<<<BB * NN, 256>>>(norm_w, norm_b, bank_upd);
}